// round 4
// baseline (speedup 1.0000x reference)
#include <cuda_runtime.h>
#include <math.h>

#define CDIM 256
#define HEADS 8
#define SCALE_ATT 0.17677669529663687f   // 32^-0.5
#define NMAXN 50000
#define EMAXE 800000

// ---------------- scratch (static device globals: no allocation allowed) ----
__device__ float    g_Q   [(size_t)NMAXN * CDIM];
__device__ float    g_K   [(size_t)NMAXN * CDIM];
__device__ float    g_V   [(size_t)NMAXN * CDIM];
__device__ float    g_attn[(size_t)NMAXN * CDIM];
__device__ float    g_y1  [(size_t)NMAXN * CDIM];
__device__ float    g_h   [(size_t)NMAXN * 512];
__device__ float    g_t2  [(size_t)NMAXN * CDIM];
__device__ float    g_sc  [(size_t)EMAXE * HEADS];
__device__ unsigned g_amax[(size_t)NMAXN * HEADS];
__device__ float    g_asum[(size_t)NMAXN * HEADS];
__device__ int      g_is64;

// ---------------- edge-index dtype detection --------------------------------
// If the data is really int32, interpreting as int64 gives lo + hi*2^32 which
// is >= N with probability ~1 per element. All-in-range over 256 samples
// => genuinely int64.
__global__ void detect64_kernel(const void* ei, int N) {
    const long long* p = (const long long*)ei;
    int ok = 1;
    for (int i = 0; i < 256; i++) {
        long long v = p[i];
        if (v < 0 || v >= (long long)N) { ok = 0; break; }
    }
    g_is64 = ok;
}

__device__ __forceinline__ int edge_idx(const void* ei, size_t off) {
    if (g_is64) return (int)((const long long*)ei)[off];
    return ((const int*)ei)[off];
}

// ---------------- init ------------------------------------------------------
__global__ void init_kernel(int N) {
    int i = blockIdx.x * blockDim.x + threadIdx.x;
    if (i < N * CDIM) g_attn[i] = 0.0f;
    if (i < N * HEADS) {
        g_amax[i] = 0x80000000u;   // encoded +0.0 (matches torch include_self max-with-zeros)
        g_asum[i] = 0.0f;
    }
}

// ---------------- SGEMM: C[M,Nc] = A[M,K] @ B[K,Nc] (+bias)(+gelu) ----------
// 128x128 block tile, BK=8, 256 threads, 8x8 per-thread microtile.
template <int EPI>   // 0 = none, 1 = +bias, 2 = +bias, gelu
__global__ void __launch_bounds__(256)
sgemm_kernel(const float* __restrict__ A, const float* __restrict__ B,
             const float* __restrict__ bias, float* __restrict__ C,
             int M, int Nc, int K)
{
    __shared__ float As[8][128];
    __shared__ float Bs[8][128];

    const int tid  = threadIdx.x;
    const int brow = blockIdx.y * 128;
    const int bcol = blockIdx.x * 128;
    const int tx = tid & 15;          // 16 cols of threads
    const int ty = tid >> 4;          // 16 rows of threads

    float acc[8][8];
    #pragma unroll
    for (int i = 0; i < 8; i++)
        #pragma unroll
        for (int j = 0; j < 8; j++) acc[i][j] = 0.0f;

    const int aRow = tid >> 1;            // 0..127
    const int aCol = (tid & 1) * 4;       // 0 or 4
    const int bRow = tid >> 5;            // 0..7
    const int bCol = (tid & 31) * 4;      // 0..124

    const int  gr     = brow + aRow;
    const bool avalid = (gr < M);
    const float* ap = A + (size_t)(avalid ? gr : 0) * K + aCol;

    for (int k0 = 0; k0 < K; k0 += 8) {
        float4 av = *(const float4*)(ap + k0);
        if (!avalid) av = make_float4(0.f, 0.f, 0.f, 0.f);
        As[aCol + 0][aRow] = av.x;
        As[aCol + 1][aRow] = av.y;
        As[aCol + 2][aRow] = av.z;
        As[aCol + 3][aRow] = av.w;
        *(float4*)&Bs[bRow][bCol] =
            *(const float4*)(B + (size_t)(k0 + bRow) * Nc + bcol + bCol);
        __syncthreads();

        #pragma unroll
        for (int kk = 0; kk < 8; kk++) {
            float a[8], b[8];
            #pragma unroll
            for (int i = 0; i < 8; i++) a[i] = As[kk][ty * 8 + i];
            #pragma unroll
            for (int j = 0; j < 8; j++) b[j] = Bs[kk][tx * 8 + j];
            #pragma unroll
            for (int i = 0; i < 8; i++)
                #pragma unroll
                for (int j = 0; j < 8; j++) acc[i][j] += a[i] * b[j];
        }
        __syncthreads();
    }

    float bs[8];
    if (EPI >= 1) {
        #pragma unroll
        for (int j = 0; j < 8; j++) bs[j] = bias[bcol + tx * 8 + j];
    }

    #pragma unroll
    for (int i = 0; i < 8; i++) {
        int row = brow + ty * 8 + i;
        if (row >= M) continue;
        float v[8];
        #pragma unroll
        for (int j = 0; j < 8; j++) {
            float t = acc[i][j];
            if (EPI >= 1) t += bs[j];
            if (EPI == 2) t = 0.5f * t * (1.0f + erff(t * 0.7071067811865476f));
            v[j] = t;
        }
        float* cp = C + (size_t)row * Nc + bcol + tx * 8;
        *(float4*)(cp)     = make_float4(v[0], v[1], v[2], v[3]);
        *(float4*)(cp + 4) = make_float4(v[4], v[5], v[6], v[7]);
    }
}

// ---------------- edge pass 1: scores + segmented max -----------------------
// One warp per edge. Lane l owns channels [8l, 8l+8) -> head l/4.
__global__ void edge_scores_kernel(const void* __restrict__ ei, int E)
{
    int gw = (blockIdx.x * blockDim.x + threadIdx.x) >> 5;
    if (gw >= E) return;
    int lane = threadIdx.x & 31;
    int src = edge_idx(ei, (size_t)gw);
    int dst = edge_idx(ei, (size_t)E + gw);

    const float4* qp = (const float4*)(g_Q + (size_t)dst * CDIM);
    const float4* kp = (const float4*)(g_K + (size_t)src * CDIM);
    float4 q0 = qp[2 * lane], q1 = qp[2 * lane + 1];
    float4 k0 = kp[2 * lane], k1 = kp[2 * lane + 1];

    float p = q0.x * k0.x + q0.y * k0.y + q0.z * k0.z + q0.w * k0.w
            + q1.x * k1.x + q1.y * k1.y + q1.z * k1.z + q1.w * k1.w;
    p += __shfl_xor_sync(0xffffffffu, p, 1);
    p += __shfl_xor_sync(0xffffffffu, p, 2);

    if ((lane & 3) == 0) {
        int h = lane >> 2;
        float s = p * SCALE_ATT;
        g_sc[(size_t)gw * HEADS + h] = s;
        // monotonic float->uint encoding for atomicMax
        unsigned u = __float_as_uint(s);
        u = (u >> 31) ? ~u : (u | 0x80000000u);
        atomicMax(&g_amax[dst * HEADS + h], u);
    }
}

// ---------------- edge pass 2: exp + segmented sum --------------------------
__global__ void edge_softmax_kernel(const void* __restrict__ ei, int E)
{
    int idx = blockIdx.x * blockDim.x + threadIdx.x;
    if (idx >= E * HEADS) return;
    int e = idx >> 3, h = idx & 7;
    int dst = edge_idx(ei, (size_t)E + e);
    unsigned u = g_amax[dst * HEADS + h];
    float m = (u >> 31) ? __uint_as_float(u & 0x7fffffffu) : __uint_as_float(~u);
    float w = expf(g_sc[idx] - m);
    g_sc[idx] = w;
    atomicAdd(&g_asum[dst * HEADS + h], w);
}

// ---------------- edge pass 3: weighted message scatter-add -----------------
__global__ void edge_message_kernel(const void* __restrict__ ei, int E)
{
    int gw = (blockIdx.x * blockDim.x + threadIdx.x) >> 5;
    if (gw >= E) return;
    int lane = threadIdx.x & 31;
    int src = edge_idx(ei, (size_t)gw);
    int dst = edge_idx(ei, (size_t)E + gw);

    float w = 0.0f;
    if (lane < HEADS)
        w = g_sc[(size_t)gw * HEADS + lane] / (g_asum[dst * HEADS + lane] + 1e-8f);
    float wn = __shfl_sync(0xffffffffu, w, lane >> 2);   // head for this lane's channels

    const float4* vp = (const float4*)(g_V + (size_t)src * CDIM);
    float4 v0 = vp[2 * lane], v1 = vp[2 * lane + 1];
    float* op = g_attn + (size_t)dst * CDIM + lane * 8;
    atomicAdd(op + 0, v0.x * wn);
    atomicAdd(op + 1, v0.y * wn);
    atomicAdd(op + 2, v0.z * wn);
    atomicAdd(op + 3, v0.w * wn);
    atomicAdd(op + 4, v1.x * wn);
    atomicAdd(op + 5, v1.y * wn);
    atomicAdd(op + 6, v1.z * wn);
    atomicAdd(op + 7, v1.w * wn);
}

// ---------------- fused residual-add + LayerNorm (warp per row) -------------
__global__ void add_ln_kernel(const float* __restrict__ A, const float* __restrict__ B,
                              const float* __restrict__ gam, const float* __restrict__ bet,
                              float* __restrict__ out, int M)
{
    int row = (blockIdx.x * blockDim.x + threadIdx.x) >> 5;
    if (row >= M) return;
    int lane = threadIdx.x & 31;

    const float4* ap = (const float4*)(A + (size_t)row * CDIM);
    const float4* bp = (const float4*)(B + (size_t)row * CDIM);
    float4 a0 = ap[2 * lane], a1 = ap[2 * lane + 1];
    float4 b0 = bp[2 * lane], b1 = bp[2 * lane + 1];
    float v[8] = { a0.x + b0.x, a0.y + b0.y, a0.z + b0.z, a0.w + b0.w,
                   a1.x + b1.x, a1.y + b1.y, a1.z + b1.z, a1.w + b1.w };

    float s = 0.f, ss = 0.f;
    #pragma unroll
    for (int i = 0; i < 8; i++) { s += v[i]; ss += v[i] * v[i]; }
    #pragma unroll
    for (int o = 16; o > 0; o >>= 1) {
        s  += __shfl_xor_sync(0xffffffffu, s,  o);
        ss += __shfl_xor_sync(0xffffffffu, ss, o);
    }
    float mu   = s * (1.0f / CDIM);
    float var  = ss * (1.0f / CDIM) - mu * mu;
    float rstd = rsqrtf(var + 1e-5f);

    const float4* gp = (const float4*)gam;
    const float4* ep = (const float4*)bet;
    float4 g0 = gp[2 * lane], g1 = gp[2 * lane + 1];
    float4 e0 = ep[2 * lane], e1 = ep[2 * lane + 1];

    float4 o0, o1;
    o0.x = (v[0] - mu) * rstd * g0.x + e0.x;
    o0.y = (v[1] - mu) * rstd * g0.y + e0.y;
    o0.z = (v[2] - mu) * rstd * g0.z + e0.z;
    o0.w = (v[3] - mu) * rstd * g0.w + e0.w;
    o1.x = (v[4] - mu) * rstd * g1.x + e1.x;
    o1.y = (v[5] - mu) * rstd * g1.y + e1.y;
    o1.z = (v[6] - mu) * rstd * g1.z + e1.z;
    o1.w = (v[7] - mu) * rstd * g1.w + e1.w;

    float4* op = (float4*)(out + (size_t)row * CDIM);
    op[2 * lane]     = o0;
    op[2 * lane + 1] = o1;
}

// ---------------- host side -------------------------------------------------
static void launch_gemm(const float* A, const float* B, const float* bias, float* C,
                        int M, int Nc, int K, int epi)
{
    dim3 grid(Nc / 128, (M + 127) / 128);
    if (epi == 0)      sgemm_kernel<0><<<grid, 256>>>(A, B, bias, C, M, Nc, K);
    else if (epi == 1) sgemm_kernel<1><<<grid, 256>>>(A, B, bias, C, M, Nc, K);
    else               sgemm_kernel<2><<<grid, 256>>>(A, B, bias, C, M, Nc, K);
}

extern "C" void kernel_launch(void* const* d_in, const int* in_sizes, int n_in,
                              void* d_out, int out_size)
{
    const float* x    = (const float*)d_in[0];
    const void*  ei   = d_in[1];
    // d_in[2] = batch (unused)
    const float* Wq   = (const float*)d_in[3];
    const float* Wk   = (const float*)d_in[4];
    const float* Wv   = (const float*)d_in[5];
    const float* Wo   = (const float*)d_in[6];
    const float* Wob  = (const float*)d_in[7];
    const float* ln1g = (const float*)d_in[8];
    const float* ln1b = (const float*)d_in[9];
    const float* ln2g = (const float*)d_in[10];
    const float* ln2b = (const float*)d_in[11];
    const float* W1   = (const float*)d_in[12];
    const float* b1   = (const float*)d_in[13];
    const float* W2   = (const float*)d_in[14];
    const float* b2   = (const float*)d_in[15];
    float* out = (float*)d_out;

    int N = in_sizes[0] / CDIM;
    int E = in_sizes[1] / 2;

    float *pQ, *pK, *pV, *pAttn, *pY1, *pH, *pT2;
    cudaGetSymbolAddress((void**)&pQ,    g_Q);
    cudaGetSymbolAddress((void**)&pK,    g_K);
    cudaGetSymbolAddress((void**)&pV,    g_V);
    cudaGetSymbolAddress((void**)&pAttn, g_attn);
    cudaGetSymbolAddress((void**)&pY1,   g_y1);
    cudaGetSymbolAddress((void**)&pH,    g_h);
    cudaGetSymbolAddress((void**)&pT2,   g_t2);

    detect64_kernel<<<1, 1>>>(ei, N);
    init_kernel<<<(N * CDIM + 255) / 256, 256>>>(N);

    // Q/K/V projections
    launch_gemm(x, Wq, nullptr, pQ, N, 256, 256, 0);
    launch_gemm(x, Wk, nullptr, pK, N, 256, 256, 0);
    launch_gemm(x, Wv, nullptr, pV, N, 256, 256, 0);

    // edge attention
    edge_scores_kernel <<<(E * 32 + 255) / 256, 256>>>(ei, E);
    edge_softmax_kernel<<<(E * 8  + 255) / 256, 256>>>(ei, E);
    edge_message_kernel<<<(E * 32 + 255) / 256, 256>>>(ei, E);

    // output projection + residual LN1
    launch_gemm(pAttn, Wo, Wob, pT2, N, 256, 256, 1);
    add_ln_kernel<<<(N * 32 + 255) / 256, 256>>>(x, pT2, ln1g, ln1b, pY1, N);

    // FFN
    launch_gemm(pY1, W1, b1, pH,  N, 512, 256, 2);   // + bias + exact GELU
    launch_gemm(pH,  W2, b2, pT2, N, 256, 512, 1);   // + bias
    add_ln_kernel<<<(N * 32 + 255) / 256, 256>>>(pY1, pT2, ln2g, ln2b, out, N);
}

// round 6
// speedup vs baseline: 2.9059x; 2.9059x over previous
#include <cuda_runtime.h>
#include <math.h>

#define CDIM 256
#define HEADS 8
#define SCALE_ATT 0.17677669529663687f   // 32^-0.5
#define NMAXN 50000
#define EMAXE 800000

// ---------------- scratch (static device globals: no allocation allowed) ----
__device__ float    g_Q   [(size_t)NMAXN * CDIM];
__device__ float    g_K   [(size_t)NMAXN * CDIM];
__device__ float    g_V   [(size_t)NMAXN * CDIM];
__device__ float    g_attn[(size_t)NMAXN * CDIM];
__device__ float    g_y1  [(size_t)NMAXN * CDIM];
__device__ float    g_h   [(size_t)NMAXN * 512];
__device__ float    g_t2  [(size_t)NMAXN * CDIM];
__device__ float    g_sc  [(size_t)EMAXE * HEADS];
__device__ unsigned g_amax[(size_t)NMAXN * HEADS];
__device__ float    g_asum[(size_t)NMAXN * HEADS];
__device__ int      g_is64;

// ---------------- edge-index dtype detection --------------------------------
__global__ void detect64_kernel(const void* ei, int N) {
    const long long* p = (const long long*)ei;
    int ok = 1;
    for (int i = 0; i < 256; i++) {
        long long v = p[i];
        if (v < 0 || v >= (long long)N) { ok = 0; break; }
    }
    g_is64 = ok;
}

__device__ __forceinline__ int edge_idx(const void* ei, size_t off) {
    if (g_is64) return (int)((const long long*)ei)[off];
    return ((const int*)ei)[off];
}

// ---------------- init ------------------------------------------------------
__global__ void init_kernel(int N) {
    int i = blockIdx.x * blockDim.x + threadIdx.x;
    if (i < N * (CDIM / 4)) ((float4*)g_attn)[i] = make_float4(0.f, 0.f, 0.f, 0.f);
    if (i < N * HEADS) {
        g_amax[i] = 0x80000000u;   // encoded +0.0 (matches torch include_self max-with-zeros)
        g_asum[i] = 0.0f;
    }
}

// ---------------- TF32 tensor-core GEMM -------------------------------------
// C[M,Nc] = A[M,K] @ B[K,Nc] (+bias)(+gelu). 128x128 tile, BK=16, cp.async
// double buffer, mma.sync m16n8k8 tf32. 256 threads = 8 warps (2m x 4n),
// warp tile 64x32 = 4x4 mma tiles.
__device__ __forceinline__ unsigned f2tf32(float x) {
    unsigned r;
    asm("cvt.rna.tf32.f32 %0, %1;" : "=r"(r) : "f"(x));
    return r;
}

template <int EPI>   // 0 = none, 1 = +bias, 2 = +bias+gelu
__global__ void __launch_bounds__(256, 2)
tf32gemm_kernel(const float* __restrict__ A, const float* __restrict__ B,
                const float* __restrict__ bias, float* __restrict__ C,
                int M, int Nc, int K)
{
    __shared__ float As[2][128][20];   // [buf][m][k], pad 4
    __shared__ float Bs[2][16][132];   // [buf][k][n], pad 4

    const int tid  = threadIdx.x;
    const int brow = blockIdx.y * 128;
    const int bcol = blockIdx.x * 128;
    const int lane = tid & 31;
    const int warp = tid >> 5;
    const int wm = (warp >> 2) * 64;   // warp m origin within tile
    const int wn = (warp & 3) * 32;    // warp n origin within tile
    const int gid = lane >> 2;         // 0..7
    const int tig = lane & 3;          // 0..3

    float acc[4][4][4];
    #pragma unroll
    for (int mt = 0; mt < 4; mt++)
        #pragma unroll
        for (int nt = 0; nt < 4; nt++)
            #pragma unroll
            for (int i = 0; i < 4; i++) acc[mt][nt][i] = 0.0f;

    // cp.async stage loader: A 128x16 (512 float4), B 16x128 (512 float4)
    auto load_stage = [&](int buf, int k0) {
        #pragma unroll
        for (int i = 0; i < 2; i++) {
            int f = tid + i * 256;
            int r = f >> 2, q = (f & 3) * 4;
            const float* src = A + (size_t)(brow + r) * K + k0 + q;
            unsigned dst = (unsigned)__cvta_generic_to_shared(&As[buf][r][q]);
            int sz = (brow + r < M) ? 16 : 0;
            asm volatile("cp.async.cg.shared.global [%0], [%1], 16, %2;\n"
                         :: "r"(dst), "l"(src), "r"(sz));
        }
        #pragma unroll
        for (int i = 0; i < 2; i++) {
            int f = tid + i * 256;
            int r = f >> 5, q = (f & 31) * 4;
            const float* src = B + (size_t)(k0 + r) * Nc + bcol + q;
            unsigned dst = (unsigned)__cvta_generic_to_shared(&Bs[buf][r][q]);
            asm volatile("cp.async.cg.shared.global [%0], [%1], 16;\n"
                         :: "r"(dst), "l"(src));
        }
    };

    const int KT = K >> 4;
    load_stage(0, 0);
    asm volatile("cp.async.commit_group;\n");

    for (int kt = 0; kt < KT; kt++) {
        const int cur = kt & 1;
        if (kt + 1 < KT) {
            load_stage(cur ^ 1, (kt + 1) << 4);
            asm volatile("cp.async.commit_group;\n");
            asm volatile("cp.async.wait_group 1;\n");
        } else {
            asm volatile("cp.async.wait_group 0;\n");
        }
        __syncthreads();

        #pragma unroll
        for (int k8 = 0; k8 < 16; k8 += 8) {
            unsigned af[4][4], bf[4][2];
            const int kk = k8 + tig;
            #pragma unroll
            for (int mt = 0; mt < 4; mt++) {
                int m0 = wm + mt * 16 + gid;
                af[mt][0] = f2tf32(As[cur][m0    ][kk    ]);
                af[mt][1] = f2tf32(As[cur][m0 + 8][kk    ]);
                af[mt][2] = f2tf32(As[cur][m0    ][kk + 4]);
                af[mt][3] = f2tf32(As[cur][m0 + 8][kk + 4]);
            }
            #pragma unroll
            for (int nt = 0; nt < 4; nt++) {
                int n0 = wn + nt * 8 + gid;
                bf[nt][0] = f2tf32(Bs[cur][kk    ][n0]);
                bf[nt][1] = f2tf32(Bs[cur][kk + 4][n0]);
            }
            #pragma unroll
            for (int mt = 0; mt < 4; mt++)
                #pragma unroll
                for (int nt = 0; nt < 4; nt++) {
                    asm volatile(
                        "mma.sync.aligned.m16n8k8.row.col.f32.tf32.tf32.f32 "
                        "{%0,%1,%2,%3}, {%4,%5,%6,%7}, {%8,%9}, {%0,%1,%2,%3};\n"
                        : "+f"(acc[mt][nt][0]), "+f"(acc[mt][nt][1]),
                          "+f"(acc[mt][nt][2]), "+f"(acc[mt][nt][3])
                        : "r"(af[mt][0]), "r"(af[mt][1]), "r"(af[mt][2]), "r"(af[mt][3]),
                          "r"(bf[nt][0]), "r"(bf[nt][1]));
                }
        }
        __syncthreads();
    }

    // epilogue
    #pragma unroll
    for (int mt = 0; mt < 4; mt++) {
        #pragma unroll
        for (int nt = 0; nt < 4; nt++) {
            int r = brow + wm + mt * 16 + gid;
            int c = bcol + wn + nt * 8 + tig * 2;
            float v0 = acc[mt][nt][0], v1 = acc[mt][nt][1];
            float v2 = acc[mt][nt][2], v3 = acc[mt][nt][3];
            if (EPI >= 1) {
                float b0 = bias[c], b1 = bias[c + 1];
                v0 += b0; v1 += b1; v2 += b0; v3 += b1;
            }
            if (EPI == 2) {
                v0 = 0.5f * v0 * (1.0f + erff(v0 * 0.7071067811865476f));
                v1 = 0.5f * v1 * (1.0f + erff(v1 * 0.7071067811865476f));
                v2 = 0.5f * v2 * (1.0f + erff(v2 * 0.7071067811865476f));
                v3 = 0.5f * v3 * (1.0f + erff(v3 * 0.7071067811865476f));
            }
            if (r < M)     *(float2*)(C + (size_t)r       * Nc + c) = make_float2(v0, v1);
            if (r + 8 < M) *(float2*)(C + (size_t)(r + 8) * Nc + c) = make_float2(v2, v3);
        }
    }
}

// ---------------- edge pass 1: scores + segmented max -----------------------
__global__ void edge_scores_kernel(const void* __restrict__ ei, int E)
{
    int gw = (blockIdx.x * blockDim.x + threadIdx.x) >> 5;
    if (gw >= E) return;
    int lane = threadIdx.x & 31;
    int src = edge_idx(ei, (size_t)gw);
    int dst = edge_idx(ei, (size_t)E + gw);

    const float4* qp = (const float4*)(g_Q + (size_t)dst * CDIM);
    const float4* kp = (const float4*)(g_K + (size_t)src * CDIM);
    float4 q0 = qp[2 * lane], q1 = qp[2 * lane + 1];
    float4 k0 = kp[2 * lane], k1 = kp[2 * lane + 1];

    float p = q0.x * k0.x + q0.y * k0.y + q0.z * k0.z + q0.w * k0.w
            + q1.x * k1.x + q1.y * k1.y + q1.z * k1.z + q1.w * k1.w;
    p += __shfl_xor_sync(0xffffffffu, p, 1);
    p += __shfl_xor_sync(0xffffffffu, p, 2);

    if ((lane & 3) == 0) {
        int h = lane >> 2;
        float s = p * SCALE_ATT;
        g_sc[(size_t)gw * HEADS + h] = s;
        unsigned u = __float_as_uint(s);
        u = (u >> 31) ? ~u : (u | 0x80000000u);
        atomicMax(&g_amax[dst * HEADS + h], u);
    }
}

// ---------------- edge pass 2: exp + segmented sum --------------------------
__global__ void edge_softmax_kernel(const void* __restrict__ ei, int E)
{
    int idx = blockIdx.x * blockDim.x + threadIdx.x;
    if (idx >= E * HEADS) return;
    int e = idx >> 3, h = idx & 7;
    int dst = edge_idx(ei, (size_t)E + e);
    unsigned u = g_amax[dst * HEADS + h];
    float m = (u >> 31) ? __uint_as_float(u & 0x7fffffffu) : __uint_as_float(~u);
    float w = expf(g_sc[idx] - m);
    g_sc[idx] = w;
    atomicAdd(&g_asum[dst * HEADS + h], w);
}

// ---------------- edge pass 3: weighted message scatter-add (v4 red) --------
__global__ void edge_message_kernel(const void* __restrict__ ei, int E)
{
    int gw = (blockIdx.x * blockDim.x + threadIdx.x) >> 5;
    if (gw >= E) return;
    int lane = threadIdx.x & 31;
    int src = edge_idx(ei, (size_t)gw);
    int dst = edge_idx(ei, (size_t)E + gw);

    float w = 0.0f;
    if (lane < HEADS)
        w = g_sc[(size_t)gw * HEADS + lane] / (g_asum[dst * HEADS + lane] + 1e-8f);
    float wn = __shfl_sync(0xffffffffu, w, lane >> 2);

    const float4* vp = (const float4*)(g_V + (size_t)src * CDIM);
    float4 v0 = vp[2 * lane], v1 = vp[2 * lane + 1];
    float* op = g_attn + (size_t)dst * CDIM + lane * 8;
    asm volatile("red.global.add.v4.f32 [%0], {%1,%2,%3,%4};\n"
                 :: "l"(op), "f"(v0.x * wn), "f"(v0.y * wn),
                    "f"(v0.z * wn), "f"(v0.w * wn) : "memory");
    asm volatile("red.global.add.v4.f32 [%0], {%1,%2,%3,%4};\n"
                 :: "l"(op + 4), "f"(v1.x * wn), "f"(v1.y * wn),
                    "f"(v1.z * wn), "f"(v1.w * wn) : "memory");
}

// ---------------- fused residual-add + LayerNorm (warp per row) -------------
__global__ void add_ln_kernel(const float* __restrict__ A, const float* __restrict__ B,
                              const float* __restrict__ gam, const float* __restrict__ bet,
                              float* __restrict__ out, int M)
{
    int row = (blockIdx.x * blockDim.x + threadIdx.x) >> 5;
    if (row >= M) return;
    int lane = threadIdx.x & 31;

    const float4* ap = (const float4*)(A + (size_t)row * CDIM);
    const float4* bp = (const float4*)(B + (size_t)row * CDIM);
    float4 a0 = ap[2 * lane], a1 = ap[2 * lane + 1];
    float4 b0 = bp[2 * lane], b1 = bp[2 * lane + 1];
    float v[8] = { a0.x + b0.x, a0.y + b0.y, a0.z + b0.z, a0.w + b0.w,
                   a1.x + b1.x, a1.y + b1.y, a1.z + b1.z, a1.w + b1.w };

    float s = 0.f, ss = 0.f;
    #pragma unroll
    for (int i = 0; i < 8; i++) { s += v[i]; ss += v[i] * v[i]; }
    #pragma unroll
    for (int o = 16; o > 0; o >>= 1) {
        s  += __shfl_xor_sync(0xffffffffu, s,  o);
        ss += __shfl_xor_sync(0xffffffffu, ss, o);
    }
    float mu   = s * (1.0f / CDIM);
    float var  = ss * (1.0f / CDIM) - mu * mu;
    float rstd = rsqrtf(var + 1e-5f);

    const float4* gp = (const float4*)gam;
    const float4* ep = (const float4*)bet;
    float4 g0 = gp[2 * lane], g1 = gp[2 * lane + 1];
    float4 e0 = ep[2 * lane], e1 = ep[2 * lane + 1];

    float4 o0, o1;
    o0.x = (v[0] - mu) * rstd * g0.x + e0.x;
    o0.y = (v[1] - mu) * rstd * g0.y + e0.y;
    o0.z = (v[2] - mu) * rstd * g0.z + e0.z;
    o0.w = (v[3] - mu) * rstd * g0.w + e0.w;
    o1.x = (v[4] - mu) * rstd * g1.x + e1.x;
    o1.y = (v[5] - mu) * rstd * g1.y + e1.y;
    o1.z = (v[6] - mu) * rstd * g1.z + e1.z;
    o1.w = (v[7] - mu) * rstd * g1.w + e1.w;

    float4* op = (float4*)(out + (size_t)row * CDIM);
    op[2 * lane]     = o0;
    op[2 * lane + 1] = o1;
}

// ---------------- host side -------------------------------------------------
static void launch_gemm(const float* A, const float* B, const float* bias, float* C,
                        int M, int Nc, int K, int epi)
{
    dim3 grid(Nc / 128, (M + 127) / 128);
    if (epi == 0)      tf32gemm_kernel<0><<<grid, 256>>>(A, B, bias, C, M, Nc, K);
    else if (epi == 1) tf32gemm_kernel<1><<<grid, 256>>>(A, B, bias, C, M, Nc, K);
    else               tf32gemm_kernel<2><<<grid, 256>>>(A, B, bias, C, M, Nc, K);
}

extern "C" void kernel_launch(void* const* d_in, const int* in_sizes, int n_in,
                              void* d_out, int out_size)
{
    const float* x    = (const float*)d_in[0];
    const void*  ei   = d_in[1];
    const float* Wq   = (const float*)d_in[3];
    const float* Wk   = (const float*)d_in[4];
    const float* Wv   = (const float*)d_in[5];
    const float* Wo   = (const float*)d_in[6];
    const float* Wob  = (const float*)d_in[7];
    const float* ln1g = (const float*)d_in[8];
    const float* ln1b = (const float*)d_in[9];
    const float* ln2g = (const float*)d_in[10];
    const float* ln2b = (const float*)d_in[11];
    const float* W1   = (const float*)d_in[12];
    const float* b1   = (const float*)d_in[13];
    const float* W2   = (const float*)d_in[14];
    const float* b2   = (const float*)d_in[15];
    float* out = (float*)d_out;

    int N = in_sizes[0] / CDIM;
    int E = in_sizes[1] / 2;

    float *pQ, *pK, *pV, *pAttn, *pY1, *pH, *pT2;
    cudaGetSymbolAddress((void**)&pQ,    g_Q);
    cudaGetSymbolAddress((void**)&pK,    g_K);
    cudaGetSymbolAddress((void**)&pV,    g_V);
    cudaGetSymbolAddress((void**)&pAttn, g_attn);
    cudaGetSymbolAddress((void**)&pY1,   g_y1);
    cudaGetSymbolAddress((void**)&pH,    g_h);
    cudaGetSymbolAddress((void**)&pT2,   g_t2);

    detect64_kernel<<<1, 1>>>(ei, N);
    init_kernel<<<(N * CDIM / 4 + 255) / 256, 256>>>(N);

    // Q/K/V projections
    launch_gemm(x, Wq, nullptr, pQ, N, 256, 256, 0);
    launch_gemm(x, Wk, nullptr, pK, N, 256, 256, 0);
    launch_gemm(x, Wv, nullptr, pV, N, 256, 256, 0);

    // edge attention
    edge_scores_kernel <<<(E * 32 + 255) / 256, 256>>>(ei, E);
    edge_softmax_kernel<<<(E * 8  + 255) / 256, 256>>>(ei, E);
    edge_message_kernel<<<(E * 32 + 255) / 256, 256>>>(ei, E);

    // output projection + residual LN1
    launch_gemm(pAttn, Wo, Wob, pT2, N, 256, 256, 1);
    add_ln_kernel<<<(N * 32 + 255) / 256, 256>>>(x, pT2, ln1g, ln1b, pY1, N);

    // FFN
    launch_gemm(pY1, W1, b1, pH,  N, 512, 256, 2);   // + bias + exact GELU
    launch_gemm(pH,  W2, b2, pT2, N, 256, 512, 1);   // + bias
    add_ln_kernel<<<(N * 32 + 255) / 256, 256>>>(pY1, pT2, ln2g, ln2b, out, N);
}

// round 7
// speedup vs baseline: 3.4730x; 1.1952x over previous
#include <cuda_runtime.h>
#include <math.h>

#define CDIM 256
#define HEADS 8
#define SCALE_ATT 0.17677669529663687f   // 32^-0.5
#define NMAXN 50000
#define EMAXE 800000

// ---------------- scratch (static device globals: no allocation allowed) ----
__device__ float    g_Q   [(size_t)NMAXN * CDIM];
__device__ float    g_K   [(size_t)NMAXN * CDIM];
__device__ float    g_V   [(size_t)NMAXN * CDIM];
__device__ float    g_attn[(size_t)NMAXN * CDIM];
__device__ float    g_y1  [(size_t)NMAXN * CDIM];
__device__ float    g_h   [(size_t)NMAXN * 512];
__device__ float    g_t2  [(size_t)NMAXN * CDIM];
__device__ float    g_sc  [(size_t)EMAXE * HEADS];
__device__ int      g_deg [NMAXN];
__device__ int      g_cnt [NMAXN];
__device__ int      g_off [NMAXN + 1];
__device__ int      g_srcs[EMAXE];
__device__ int      g_is64;

// ---------------- edge-index dtype detection --------------------------------
__global__ void detect64_kernel(const void* ei, int N) {
    const long long* p = (const long long*)ei;
    int ok = 1;
    for (int i = 0; i < 256; i++) {
        long long v = p[i];
        if (v < 0 || v >= (long long)N) { ok = 0; break; }
    }
    g_is64 = ok;
}

__device__ __forceinline__ int edge_idx(const void* ei, size_t off) {
    if (g_is64) return (int)((const long long*)ei)[off];
    return ((const int*)ei)[off];
}

// ---------------- counting sort of edges by dst -----------------------------
__global__ void zero_kernel(int N) {
    int i = blockIdx.x * blockDim.x + threadIdx.x;
    if (i < N) { g_deg[i] = 0; g_cnt[i] = 0; }
}

__global__ void hist_kernel(const void* __restrict__ ei, int E) {
    int e = blockIdx.x * blockDim.x + threadIdx.x;
    if (e >= E) return;
    int dst = edge_idx(ei, (size_t)E + e);
    atomicAdd(&g_deg[dst], 1);
}

// exclusive prefix sum, single block of 1024 threads over sequential tiles
__global__ void scan_kernel(int N) {
    __shared__ int s[1024];
    __shared__ int carry_s;
    int tid = threadIdx.x;
    if (tid == 0) carry_s = 0;
    __syncthreads();
    for (int base = 0; base < N; base += 1024) {
        int i = base + tid;
        int v = (i < N) ? g_deg[i] : 0;
        s[tid] = v;
        __syncthreads();
        #pragma unroll
        for (int o = 1; o < 1024; o <<= 1) {
            int t = (tid >= o) ? s[tid - o] : 0;
            __syncthreads();
            s[tid] += t;
            __syncthreads();
        }
        int carry = carry_s;
        if (i < N) g_off[i] = carry + s[tid] - v;   // exclusive
        __syncthreads();
        if (tid == 1023) carry_s = carry + s[1023];
        __syncthreads();
    }
    if (tid == 0) g_off[N] = carry_s;
}

__global__ void scatter_kernel(const void* __restrict__ ei, int E) {
    int e = blockIdx.x * blockDim.x + threadIdx.x;
    if (e >= E) return;
    int src = edge_idx(ei, (size_t)e);
    int dst = edge_idx(ei, (size_t)E + e);
    int pos = g_off[dst] + atomicAdd(&g_cnt[dst], 1);
    g_srcs[pos] = src;
}

// ---------------- TF32 tensor-core GEMM -------------------------------------
// C[M,Nc] = A[M,K] @ B[K,Nc] (+bias)(+gelu). 128x128 tile, BK=16, cp.async
// double buffer, mma.sync m16n8k8 tf32 (truncation mode: raw f32 bits).
__device__ __forceinline__ unsigned f2tf32(float x) {
    return __float_as_uint(x);   // HMMA.TF32 ignores low mantissa bits
}

template <int EPI>   // 0 = none, 1 = +bias, 2 = +bias+gelu
__global__ void __launch_bounds__(256, 2)
tf32gemm_kernel(const float* __restrict__ A, const float* __restrict__ B,
                const float* __restrict__ bias, float* __restrict__ C,
                int M, int Nc, int K)
{
    __shared__ float As[2][128][20];   // [buf][m][k], pad 4
    __shared__ float Bs[2][16][132];   // [buf][k][n], pad 4

    const int tid  = threadIdx.x;
    const int brow = blockIdx.y * 128;
    const int bcol = blockIdx.x * 128;
    const int lane = tid & 31;
    const int warp = tid >> 5;
    const int wm = (warp >> 2) * 64;
    const int wn = (warp & 3) * 32;
    const int gid = lane >> 2;
    const int tig = lane & 3;

    float acc[4][4][4];
    #pragma unroll
    for (int mt = 0; mt < 4; mt++)
        #pragma unroll
        for (int nt = 0; nt < 4; nt++)
            #pragma unroll
            for (int i = 0; i < 4; i++) acc[mt][nt][i] = 0.0f;

    auto load_stage = [&](int buf, int k0) {
        #pragma unroll
        for (int i = 0; i < 2; i++) {
            int f = tid + i * 256;
            int r = f >> 2, q = (f & 3) * 4;
            const float* src = A + (size_t)(brow + r) * K + k0 + q;
            unsigned dst = (unsigned)__cvta_generic_to_shared(&As[buf][r][q]);
            int sz = (brow + r < M) ? 16 : 0;
            asm volatile("cp.async.cg.shared.global [%0], [%1], 16, %2;\n"
                         :: "r"(dst), "l"(src), "r"(sz));
        }
        #pragma unroll
        for (int i = 0; i < 2; i++) {
            int f = tid + i * 256;
            int r = f >> 5, q = (f & 31) * 4;
            const float* src = B + (size_t)(k0 + r) * Nc + bcol + q;
            unsigned dst = (unsigned)__cvta_generic_to_shared(&Bs[buf][r][q]);
            asm volatile("cp.async.cg.shared.global [%0], [%1], 16;\n"
                         :: "r"(dst), "l"(src));
        }
    };

    const int KT = K >> 4;
    load_stage(0, 0);
    asm volatile("cp.async.commit_group;\n");

    for (int kt = 0; kt < KT; kt++) {
        const int cur = kt & 1;
        if (kt + 1 < KT) {
            load_stage(cur ^ 1, (kt + 1) << 4);
            asm volatile("cp.async.commit_group;\n");
            asm volatile("cp.async.wait_group 1;\n");
        } else {
            asm volatile("cp.async.wait_group 0;\n");
        }
        __syncthreads();

        #pragma unroll
        for (int k8 = 0; k8 < 16; k8 += 8) {
            unsigned af[4][4], bf[4][2];
            const int kk = k8 + tig;
            #pragma unroll
            for (int mt = 0; mt < 4; mt++) {
                int m0 = wm + mt * 16 + gid;
                af[mt][0] = f2tf32(As[cur][m0    ][kk    ]);
                af[mt][1] = f2tf32(As[cur][m0 + 8][kk    ]);
                af[mt][2] = f2tf32(As[cur][m0    ][kk + 4]);
                af[mt][3] = f2tf32(As[cur][m0 + 8][kk + 4]);
            }
            #pragma unroll
            for (int nt = 0; nt < 4; nt++) {
                int n0 = wn + nt * 8 + gid;
                bf[nt][0] = f2tf32(Bs[cur][kk    ][n0]);
                bf[nt][1] = f2tf32(Bs[cur][kk + 4][n0]);
            }
            #pragma unroll
            for (int mt = 0; mt < 4; mt++)
                #pragma unroll
                for (int nt = 0; nt < 4; nt++) {
                    asm volatile(
                        "mma.sync.aligned.m16n8k8.row.col.f32.tf32.tf32.f32 "
                        "{%0,%1,%2,%3}, {%4,%5,%6,%7}, {%8,%9}, {%0,%1,%2,%3};\n"
                        : "+f"(acc[mt][nt][0]), "+f"(acc[mt][nt][1]),
                          "+f"(acc[mt][nt][2]), "+f"(acc[mt][nt][3])
                        : "r"(af[mt][0]), "r"(af[mt][1]), "r"(af[mt][2]), "r"(af[mt][3]),
                          "r"(bf[nt][0]), "r"(bf[nt][1]));
                }
        }
        __syncthreads();
    }

    #pragma unroll
    for (int mt = 0; mt < 4; mt++) {
        #pragma unroll
        for (int nt = 0; nt < 4; nt++) {
            int r = brow + wm + mt * 16 + gid;
            int c = bcol + wn + nt * 8 + tig * 2;
            float v0 = acc[mt][nt][0], v1 = acc[mt][nt][1];
            float v2 = acc[mt][nt][2], v3 = acc[mt][nt][3];
            if (EPI >= 1) {
                float b0 = bias[c], b1 = bias[c + 1];
                v0 += b0; v1 += b1; v2 += b0; v3 += b1;
            }
            if (EPI == 2) {
                v0 = 0.5f * v0 * (1.0f + erff(v0 * 0.7071067811865476f));
                v1 = 0.5f * v1 * (1.0f + erff(v1 * 0.7071067811865476f));
                v2 = 0.5f * v2 * (1.0f + erff(v2 * 0.7071067811865476f));
                v3 = 0.5f * v3 * (1.0f + erff(v3 * 0.7071067811865476f));
            }
            if (r < M)     *(float2*)(C + (size_t)r       * Nc + c) = make_float2(v0, v1);
            if (r + 8 < M) *(float2*)(C + (size_t)(r + 8) * Nc + c) = make_float2(v2, v3);
        }
    }
}

// ---------------- fused edge aggregation: warp per dst, no atomics ----------
// Lane l owns channels [8l, 8l+8); head of those channels = l>>2.
// Sweep 1: K-gather, per-head scores (stored densely at sorted pos), running
// max (init 0 = reference's include_self max on zeros).
// Sweep 2: w = exp(s - m); accumulate sum and w*V; divide once at the end
// ( Σ(w/(S+eps))·v  ==  (Σ w·v)/(S+eps) ).
__global__ void edge_agg_kernel(int Nn)
{
    int d = (blockIdx.x * blockDim.x + threadIdx.x) >> 5;
    if (d >= Nn) return;
    int lane = threadIdx.x & 31;
    int beg = g_off[d], end = g_off[d + 1];
    int h = lane >> 2;

    const float4* qp = (const float4*)(g_Q + (size_t)d * CDIM);
    float4 q0 = qp[2 * lane], q1 = qp[2 * lane + 1];

    float m = 0.0f;
    for (int p = beg; p < end; p++) {
        int src = g_srcs[p];
        const float4* kp = (const float4*)(g_K + (size_t)src * CDIM);
        float4 k0 = kp[2 * lane], k1 = kp[2 * lane + 1];
        float t = q0.x * k0.x + q0.y * k0.y + q0.z * k0.z + q0.w * k0.w
                + q1.x * k1.x + q1.y * k1.y + q1.z * k1.z + q1.w * k1.w;
        t += __shfl_xor_sync(0xffffffffu, t, 1);
        t += __shfl_xor_sync(0xffffffffu, t, 2);
        float s = t * SCALE_ATT;
        if ((lane & 3) == 0) g_sc[(size_t)p * HEADS + h] = s;
        m = fmaxf(m, s);
    }

    float sum = 0.0f;
    float acc[8] = {0.f, 0.f, 0.f, 0.f, 0.f, 0.f, 0.f, 0.f};
    for (int p = beg; p < end; p++) {
        int src = g_srcs[p];
        float s = g_sc[(size_t)p * HEADS + h];
        float w = expf(s - m);
        sum += w;
        const float4* vp = (const float4*)(g_V + (size_t)src * CDIM);
        float4 v0 = vp[2 * lane], v1 = vp[2 * lane + 1];
        acc[0] += w * v0.x; acc[1] += w * v0.y;
        acc[2] += w * v0.z; acc[3] += w * v0.w;
        acc[4] += w * v1.x; acc[5] += w * v1.y;
        acc[6] += w * v1.z; acc[7] += w * v1.w;
    }

    float r = 1.0f / (sum + 1e-8f);
    float4* op = (float4*)(g_attn + (size_t)d * CDIM);
    op[2 * lane]     = make_float4(acc[0] * r, acc[1] * r, acc[2] * r, acc[3] * r);
    op[2 * lane + 1] = make_float4(acc[4] * r, acc[5] * r, acc[6] * r, acc[7] * r);
}

// ---------------- fused residual-add + LayerNorm (warp per row) -------------
__global__ void add_ln_kernel(const float* __restrict__ A, const float* __restrict__ B,
                              const float* __restrict__ gam, const float* __restrict__ bet,
                              float* __restrict__ out, int M)
{
    int row = (blockIdx.x * blockDim.x + threadIdx.x) >> 5;
    if (row >= M) return;
    int lane = threadIdx.x & 31;

    const float4* ap = (const float4*)(A + (size_t)row * CDIM);
    const float4* bp = (const float4*)(B + (size_t)row * CDIM);
    float4 a0 = ap[2 * lane], a1 = ap[2 * lane + 1];
    float4 b0 = bp[2 * lane], b1 = bp[2 * lane + 1];
    float v[8] = { a0.x + b0.x, a0.y + b0.y, a0.z + b0.z, a0.w + b0.w,
                   a1.x + b1.x, a1.y + b1.y, a1.z + b1.z, a1.w + b1.w };

    float s = 0.f, ss = 0.f;
    #pragma unroll
    for (int i = 0; i < 8; i++) { s += v[i]; ss += v[i] * v[i]; }
    #pragma unroll
    for (int o = 16; o > 0; o >>= 1) {
        s  += __shfl_xor_sync(0xffffffffu, s,  o);
        ss += __shfl_xor_sync(0xffffffffu, ss, o);
    }
    float mu   = s * (1.0f / CDIM);
    float var  = ss * (1.0f / CDIM) - mu * mu;
    float rstd = rsqrtf(var + 1e-5f);

    const float4* gp = (const float4*)gam;
    const float4* ep = (const float4*)bet;
    float4 g0 = gp[2 * lane], g1 = gp[2 * lane + 1];
    float4 e0 = ep[2 * lane], e1 = ep[2 * lane + 1];

    float4 o0, o1;
    o0.x = (v[0] - mu) * rstd * g0.x + e0.x;
    o0.y = (v[1] - mu) * rstd * g0.y + e0.y;
    o0.z = (v[2] - mu) * rstd * g0.z + e0.z;
    o0.w = (v[3] - mu) * rstd * g0.w + e0.w;
    o1.x = (v[4] - mu) * rstd * g1.x + e1.x;
    o1.y = (v[5] - mu) * rstd * g1.y + e1.y;
    o1.z = (v[6] - mu) * rstd * g1.z + e1.z;
    o1.w = (v[7] - mu) * rstd * g1.w + e1.w;

    float4* op = (float4*)(out + (size_t)row * CDIM);
    op[2 * lane]     = o0;
    op[2 * lane + 1] = o1;
}

// ---------------- host side -------------------------------------------------
static void launch_gemm(const float* A, const float* B, const float* bias, float* C,
                        int M, int Nc, int K, int epi)
{
    dim3 grid(Nc / 128, (M + 127) / 128);
    if (epi == 0)      tf32gemm_kernel<0><<<grid, 256>>>(A, B, bias, C, M, Nc, K);
    else if (epi == 1) tf32gemm_kernel<1><<<grid, 256>>>(A, B, bias, C, M, Nc, K);
    else               tf32gemm_kernel<2><<<grid, 256>>>(A, B, bias, C, M, Nc, K);
}

extern "C" void kernel_launch(void* const* d_in, const int* in_sizes, int n_in,
                              void* d_out, int out_size)
{
    const float* x    = (const float*)d_in[0];
    const void*  ei   = d_in[1];
    const float* Wq   = (const float*)d_in[3];
    const float* Wk   = (const float*)d_in[4];
    const float* Wv   = (const float*)d_in[5];
    const float* Wo   = (const float*)d_in[6];
    const float* Wob  = (const float*)d_in[7];
    const float* ln1g = (const float*)d_in[8];
    const float* ln1b = (const float*)d_in[9];
    const float* ln2g = (const float*)d_in[10];
    const float* ln2b = (const float*)d_in[11];
    const float* W1   = (const float*)d_in[12];
    const float* b1   = (const float*)d_in[13];
    const float* W2   = (const float*)d_in[14];
    const float* b2   = (const float*)d_in[15];
    float* out = (float*)d_out;

    int N = in_sizes[0] / CDIM;
    int E = in_sizes[1] / 2;

    float *pQ, *pK, *pV, *pAttn, *pY1, *pH, *pT2;
    cudaGetSymbolAddress((void**)&pQ,    g_Q);
    cudaGetSymbolAddress((void**)&pK,    g_K);
    cudaGetSymbolAddress((void**)&pV,    g_V);
    cudaGetSymbolAddress((void**)&pAttn, g_attn);
    cudaGetSymbolAddress((void**)&pY1,   g_y1);
    cudaGetSymbolAddress((void**)&pH,    g_h);
    cudaGetSymbolAddress((void**)&pT2,   g_t2);

    // edge sort (independent of GEMMs)
    detect64_kernel<<<1, 1>>>(ei, N);
    zero_kernel   <<<(N + 255) / 256, 256>>>(N);
    hist_kernel   <<<(E + 255) / 256, 256>>>(ei, E);
    scan_kernel   <<<1, 1024>>>(N);
    scatter_kernel<<<(E + 255) / 256, 256>>>(ei, E);

    // Q/K/V projections
    launch_gemm(x, Wq, nullptr, pQ, N, 256, 256, 0);
    launch_gemm(x, Wk, nullptr, pK, N, 256, 256, 0);
    launch_gemm(x, Wv, nullptr, pV, N, 256, 256, 0);

    // fused edge attention (no atomics)
    edge_agg_kernel<<<(N * 32 + 255) / 256, 256>>>(N);

    // output projection + residual LN1
    launch_gemm(pAttn, Wo, Wob, pT2, N, 256, 256, 1);
    add_ln_kernel<<<(N * 32 + 255) / 256, 256>>>(x, pT2, ln1g, ln1b, pY1, N);

    // FFN
    launch_gemm(pY1, W1, b1, pH,  N, 512, 256, 2);   // + bias + exact GELU
    launch_gemm(pH,  W2, b2, pT2, N, 256, 512, 1);   // + bias
    add_ln_kernel<<<(N * 32 + 255) / 256, 256>>>(pY1, pT2, ln2g, ln2b, out, N);
}

// round 12
// speedup vs baseline: 3.8427x; 1.1065x over previous
#include <cuda_runtime.h>
#include <math.h>

#define CDIM 256
#define HEADS 8
#define SCALE_ATT 0.17677669529663687f   // 32^-0.5
#define NMAXN 50000
#define EMAXE 800000

// ---------------- scratch (static device globals: no allocation allowed) ----
__device__ float    g_Q   [(size_t)NMAXN * CDIM];
__device__ float    g_K   [(size_t)NMAXN * CDIM];
__device__ float    g_V   [(size_t)NMAXN * CDIM];
__device__ float    g_attn[(size_t)NMAXN * CDIM];
__device__ float    g_y1  [(size_t)NMAXN * CDIM];
__device__ float    g_h   [(size_t)NMAXN * 512];
__device__ float    g_t2  [(size_t)NMAXN * CDIM];
__device__ float    g_sc  [(size_t)EMAXE * HEADS];
__device__ int      g_deg [NMAXN];
__device__ int      g_cnt [NMAXN];
__device__ int      g_off [NMAXN + 1];
__device__ int      g_bsum[64];
__device__ int      g_srcs[EMAXE];
__device__ int      g_is64;

// ---------------- edge-index dtype detection --------------------------------
__global__ void detect64_kernel(const void* ei, int N) {
    const long long* p = (const long long*)ei;
    int ok = 1;
    for (int i = 0; i < 256; i++) {
        long long v = p[i];
        if (v < 0 || v >= (long long)N) { ok = 0; break; }
    }
    g_is64 = ok;
}

__device__ __forceinline__ int edge_idx(const void* ei, size_t off) {
    if (g_is64) return (int)((const long long*)ei)[off];
    return ((const int*)ei)[off];
}

// ---------------- counting sort of edges by dst -----------------------------
__global__ void zero_kernel(int N) {
    int i = blockIdx.x * blockDim.x + threadIdx.x;
    if (i < N) { g_deg[i] = 0; g_cnt[i] = 0; }
}

__global__ void hist_kernel(const void* __restrict__ ei, int E) {
    int e = blockIdx.x * blockDim.x + threadIdx.x;
    if (e >= E) return;
    int dst = edge_idx(ei, (size_t)E + e);
    atomicAdd(&g_deg[dst], 1);
}

// -- hierarchical exclusive scan: block scans -> top scan -> offset add ------
__global__ void scan_block_kernel(int N) {
    __shared__ int wsum[32];
    int i = blockIdx.x * 1024 + threadIdx.x;
    int lane = threadIdx.x & 31, wid = threadIdx.x >> 5;
    int orig = (i < N) ? g_deg[i] : 0;
    int v = orig;
    #pragma unroll
    for (int o = 1; o < 32; o <<= 1) {
        int t = __shfl_up_sync(0xffffffffu, v, o);
        if (lane >= o) v += t;
    }
    if (lane == 31) wsum[wid] = v;
    __syncthreads();
    if (wid == 0) {
        int w = wsum[lane];
        #pragma unroll
        for (int o = 1; o < 32; o <<= 1) {
            int t = __shfl_up_sync(0xffffffffu, w, o);
            if (lane >= o) w += t;
        }
        wsum[lane] = w;
    }
    __syncthreads();
    int excl = v - orig + (wid > 0 ? wsum[wid - 1] : 0);
    if (i < N) g_off[i] = excl;
    if (threadIdx.x == 1023) g_bsum[blockIdx.x] = wsum[31];
}

__global__ void scan_top_kernel(int nb, int N) {
    // nb <= 49; one thread, trivial
    int run = 0;
    for (int b = 0; b < nb; b++) { int t = g_bsum[b]; g_bsum[b] = run; run += t; }
    g_off[N] = run;
}

__global__ void scan_add_kernel(int N) {
    int i = blockIdx.x * 1024 + threadIdx.x;
    if (i < N) g_off[i] += g_bsum[blockIdx.x];
}

__global__ void scatter_kernel(const void* __restrict__ ei, int E) {
    int e = blockIdx.x * blockDim.x + threadIdx.x;
    if (e >= E) return;
    int src = edge_idx(ei, (size_t)e);
    int dst = edge_idx(ei, (size_t)E + e);
    int pos = g_off[dst] + atomicAdd(&g_cnt[dst], 1);
    g_srcs[pos] = src;
}

// ---------------- TF32 tensor-core GEMM -------------------------------------
__device__ __forceinline__ unsigned f2tf32(float x) {
    return __float_as_uint(x);   // HMMA.TF32 ignores low mantissa bits
}

template <int EPI>   // 0 = none, 1 = +bias, 2 = +bias+gelu
__global__ void __launch_bounds__(256, 2)
tf32gemm_kernel(const float* __restrict__ A, const float* __restrict__ B,
                const float* __restrict__ bias, float* __restrict__ C,
                int M, int Nc, int K)
{
    __shared__ float As[2][128][20];
    __shared__ float Bs[2][16][132];

    const int tid  = threadIdx.x;
    const int brow = blockIdx.y * 128;
    const int bcol = blockIdx.x * 128;
    const int lane = tid & 31;
    const int warp = tid >> 5;
    const int wm = (warp >> 2) * 64;
    const int wn = (warp & 3) * 32;
    const int gid = lane >> 2;
    const int tig = lane & 3;

    float acc[4][4][4];
    #pragma unroll
    for (int mt = 0; mt < 4; mt++)
        #pragma unroll
        for (int nt = 0; nt < 4; nt++)
            #pragma unroll
            for (int i = 0; i < 4; i++) acc[mt][nt][i] = 0.0f;

    auto load_stage = [&](int buf, int k0) {
        #pragma unroll
        for (int i = 0; i < 2; i++) {
            int f = tid + i * 256;
            int r = f >> 2, q = (f & 3) * 4;
            const float* src = A + (size_t)(brow + r) * K + k0 + q;
            unsigned dst = (unsigned)__cvta_generic_to_shared(&As[buf][r][q]);
            int sz = (brow + r < M) ? 16 : 0;
            asm volatile("cp.async.cg.shared.global [%0], [%1], 16, %2;\n"
                         :: "r"(dst), "l"(src), "r"(sz));
        }
        #pragma unroll
        for (int i = 0; i < 2; i++) {
            int f = tid + i * 256;
            int r = f >> 5, q = (f & 31) * 4;
            const float* src = B + (size_t)(k0 + r) * Nc + bcol + q;
            unsigned dst = (unsigned)__cvta_generic_to_shared(&Bs[buf][r][q]);
            asm volatile("cp.async.cg.shared.global [%0], [%1], 16;\n"
                         :: "r"(dst), "l"(src));
        }
    };

    const int KT = K >> 4;
    load_stage(0, 0);
    asm volatile("cp.async.commit_group;\n");

    for (int kt = 0; kt < KT; kt++) {
        const int cur = kt & 1;
        if (kt + 1 < KT) {
            load_stage(cur ^ 1, (kt + 1) << 4);
            asm volatile("cp.async.commit_group;\n");
            asm volatile("cp.async.wait_group 1;\n");
        } else {
            asm volatile("cp.async.wait_group 0;\n");
        }
        __syncthreads();

        #pragma unroll
        for (int k8 = 0; k8 < 16; k8 += 8) {
            unsigned af[4][4], bf[4][2];
            const int kk = k8 + tig;
            #pragma unroll
            for (int mt = 0; mt < 4; mt++) {
                int m0 = wm + mt * 16 + gid;
                af[mt][0] = f2tf32(As[cur][m0    ][kk    ]);
                af[mt][1] = f2tf32(As[cur][m0 + 8][kk    ]);
                af[mt][2] = f2tf32(As[cur][m0    ][kk + 4]);
                af[mt][3] = f2tf32(As[cur][m0 + 8][kk + 4]);
            }
            #pragma unroll
            for (int nt = 0; nt < 4; nt++) {
                int n0 = wn + nt * 8 + gid;
                bf[nt][0] = f2tf32(Bs[cur][kk    ][n0]);
                bf[nt][1] = f2tf32(Bs[cur][kk + 4][n0]);
            }
            #pragma unroll
            for (int mt = 0; mt < 4; mt++)
                #pragma unroll
                for (int nt = 0; nt < 4; nt++) {
                    asm volatile(
                        "mma.sync.aligned.m16n8k8.row.col.f32.tf32.tf32.f32 "
                        "{%0,%1,%2,%3}, {%4,%5,%6,%7}, {%8,%9}, {%0,%1,%2,%3};\n"
                        : "+f"(acc[mt][nt][0]), "+f"(acc[mt][nt][1]),
                          "+f"(acc[mt][nt][2]), "+f"(acc[mt][nt][3])
                        : "r"(af[mt][0]), "r"(af[mt][1]), "r"(af[mt][2]), "r"(af[mt][3]),
                          "r"(bf[nt][0]), "r"(bf[nt][1]));
                }
        }
        __syncthreads();
    }

    #pragma unroll
    for (int mt = 0; mt < 4; mt++) {
        #pragma unroll
        for (int nt = 0; nt < 4; nt++) {
            int r = brow + wm + mt * 16 + gid;
            int c = bcol + wn + nt * 8 + tig * 2;
            float v0 = acc[mt][nt][0], v1 = acc[mt][nt][1];
            float v2 = acc[mt][nt][2], v3 = acc[mt][nt][3];
            if (EPI >= 1) {
                float b0 = bias[c], b1 = bias[c + 1];
                v0 += b0; v1 += b1; v2 += b0; v3 += b1;
            }
            if (EPI == 2) {
                v0 = 0.5f * v0 * (1.0f + erff(v0 * 0.7071067811865476f));
                v1 = 0.5f * v1 * (1.0f + erff(v1 * 0.7071067811865476f));
                v2 = 0.5f * v2 * (1.0f + erff(v2 * 0.7071067811865476f));
                v3 = 0.5f * v3 * (1.0f + erff(v3 * 0.7071067811865476f));
            }
            if (r < M)     *(float2*)(C + (size_t)r       * Nc + c) = make_float2(v0, v1);
            if (r + 8 < M) *(float2*)(C + (size_t)(r + 8) * Nc + c) = make_float2(v2, v3);
        }
    }
}

// ---------------- fused edge aggregation: warp per dst, 2x unrolled ---------
__device__ __forceinline__ float dot8(float4 a0, float4 a1, float4 b0, float4 b1) {
    return a0.x * b0.x + a0.y * b0.y + a0.z * b0.z + a0.w * b0.w
         + a1.x * b1.x + a1.y * b1.y + a1.z * b1.z + a1.w * b1.w;
}

__global__ void edge_agg_kernel(int Nn)
{
    int d = (blockIdx.x * blockDim.x + threadIdx.x) >> 5;
    if (d >= Nn) return;
    int lane = threadIdx.x & 31;
    int beg = g_off[d], end = g_off[d + 1];
    int h = lane >> 2;

    const float4* qp = (const float4*)(g_Q + (size_t)d * CDIM);
    float4 q0 = qp[2 * lane], q1 = qp[2 * lane + 1];

    // sweep 1: scores + running max (init 0 matches reference semantics)
    float m = 0.0f;
    int p = beg;
    for (; p + 2 <= end; p += 2) {
        int s0 = g_srcs[p], s1 = g_srcs[p + 1];
        const float4* ka = (const float4*)(g_K + (size_t)s0 * CDIM);
        const float4* kb = (const float4*)(g_K + (size_t)s1 * CDIM);
        float4 a0 = ka[2 * lane], a1 = ka[2 * lane + 1];
        float4 b0 = kb[2 * lane], b1 = kb[2 * lane + 1];
        float t0 = dot8(q0, q1, a0, a1);
        float t1 = dot8(q0, q1, b0, b1);
        t0 += __shfl_xor_sync(0xffffffffu, t0, 1);
        t0 += __shfl_xor_sync(0xffffffffu, t0, 2);
        t1 += __shfl_xor_sync(0xffffffffu, t1, 1);
        t1 += __shfl_xor_sync(0xffffffffu, t1, 2);
        float sc0 = t0 * SCALE_ATT, sc1 = t1 * SCALE_ATT;
        if ((lane & 3) == 0) {
            g_sc[(size_t)p * HEADS + h]       = sc0;
            g_sc[(size_t)(p + 1) * HEADS + h] = sc1;
        }
        m = fmaxf(m, fmaxf(sc0, sc1));
    }
    if (p < end) {
        int s0 = g_srcs[p];
        const float4* ka = (const float4*)(g_K + (size_t)s0 * CDIM);
        float4 a0 = ka[2 * lane], a1 = ka[2 * lane + 1];
        float t0 = dot8(q0, q1, a0, a1);
        t0 += __shfl_xor_sync(0xffffffffu, t0, 1);
        t0 += __shfl_xor_sync(0xffffffffu, t0, 2);
        float sc0 = t0 * SCALE_ATT;
        if ((lane & 3) == 0) g_sc[(size_t)p * HEADS + h] = sc0;
        m = fmaxf(m, sc0);
    }

    // sweep 2: exp + sum + weighted V accumulate; normalize once
    float sum = 0.0f;
    float acc[8] = {0.f, 0.f, 0.f, 0.f, 0.f, 0.f, 0.f, 0.f};
    p = beg;
    for (; p + 2 <= end; p += 2) {
        int s0 = g_srcs[p], s1 = g_srcs[p + 1];
        float w0 = expf(g_sc[(size_t)p * HEADS + h] - m);
        float w1 = expf(g_sc[(size_t)(p + 1) * HEADS + h] - m);
        const float4* va = (const float4*)(g_V + (size_t)s0 * CDIM);
        const float4* vb = (const float4*)(g_V + (size_t)s1 * CDIM);
        float4 a0 = va[2 * lane], a1 = va[2 * lane + 1];
        float4 b0 = vb[2 * lane], b1 = vb[2 * lane + 1];
        sum += w0 + w1;
        acc[0] += w0 * a0.x + w1 * b0.x; acc[1] += w0 * a0.y + w1 * b0.y;
        acc[2] += w0 * a0.z + w1 * b0.z; acc[3] += w0 * a0.w + w1 * b0.w;
        acc[4] += w0 * a1.x + w1 * b1.x; acc[5] += w0 * a1.y + w1 * b1.y;
        acc[6] += w0 * a1.z + w1 * b1.z; acc[7] += w0 * a1.w + w1 * b1.w;
    }
    if (p < end) {
        int s0 = g_srcs[p];
        float w0 = expf(g_sc[(size_t)p * HEADS + h] - m);
        const float4* va = (const float4*)(g_V + (size_t)s0 * CDIM);
        float4 a0 = va[2 * lane], a1 = va[2 * lane + 1];
        sum += w0;
        acc[0] += w0 * a0.x; acc[1] += w0 * a0.y;
        acc[2] += w0 * a0.z; acc[3] += w0 * a0.w;
        acc[4] += w0 * a1.x; acc[5] += w0 * a1.y;
        acc[6] += w0 * a1.z; acc[7] += w0 * a1.w;
    }

    float r = 1.0f / (sum + 1e-8f);
    float4* op = (float4*)(g_attn + (size_t)d * CDIM);
    op[2 * lane]     = make_float4(acc[0] * r, acc[1] * r, acc[2] * r, acc[3] * r);
    op[2 * lane + 1] = make_float4(acc[4] * r, acc[5] * r, acc[6] * r, acc[7] * r);
}

// ---------------- fused residual-add + LayerNorm (warp per row) -------------
__global__ void add_ln_kernel(const float* __restrict__ A, const float* __restrict__ B,
                              const float* __restrict__ gam, const float* __restrict__ bet,
                              float* __restrict__ out, int M)
{
    int row = (blockIdx.x * blockDim.x + threadIdx.x) >> 5;
    if (row >= M) return;
    int lane = threadIdx.x & 31;

    const float4* ap = (const float4*)(A + (size_t)row * CDIM);
    const float4* bp = (const float4*)(B + (size_t)row * CDIM);
    float4 a0 = ap[2 * lane], a1 = ap[2 * lane + 1];
    float4 b0 = bp[2 * lane], b1 = bp[2 * lane + 1];
    float v[8] = { a0.x + b0.x, a0.y + b0.y, a0.z + b0.z, a0.w + b0.w,
                   a1.x + b1.x, a1.y + b1.y, a1.z + b1.z, a1.w + b1.w };

    float s = 0.f, ss = 0.f;
    #pragma unroll
    for (int i = 0; i < 8; i++) { s += v[i]; ss += v[i] * v[i]; }
    #pragma unroll
    for (int o = 16; o > 0; o >>= 1) {
        s  += __shfl_xor_sync(0xffffffffu, s,  o);
        ss += __shfl_xor_sync(0xffffffffu, ss, o);
    }
    float mu   = s * (1.0f / CDIM);
    float var  = ss * (1.0f / CDIM) - mu * mu;
    float rstd = rsqrtf(var + 1e-5f);

    const float4* gp = (const float4*)gam;
    const float4* ep = (const float4*)bet;
    float4 g0 = gp[2 * lane], g1 = gp[2 * lane + 1];
    float4 e0 = ep[2 * lane], e1 = ep[2 * lane + 1];

    float4 o0, o1;
    o0.x = (v[0] - mu) * rstd * g0.x + e0.x;
    o0.y = (v[1] - mu) * rstd * g0.y + e0.y;
    o0.z = (v[2] - mu) * rstd * g0.z + e0.z;
    o0.w = (v[3] - mu) * rstd * g0.w + e0.w;
    o1.x = (v[4] - mu) * rstd * g1.x + e1.x;
    o1.y = (v[5] - mu) * rstd * g1.y + e1.y;
    o1.z = (v[6] - mu) * rstd * g1.z + e1.z;
    o1.w = (v[7] - mu) * rstd * g1.w + e1.w;

    float4* op = (float4*)(out + (size_t)row * CDIM);
    op[2 * lane]     = o0;
    op[2 * lane + 1] = o1;
}

// ---------------- host side -------------------------------------------------
static void launch_gemm(const float* A, const float* B, const float* bias, float* C,
                        int M, int Nc, int K, int epi)
{
    dim3 grid(Nc / 128, (M + 127) / 128);
    if (epi == 0)      tf32gemm_kernel<0><<<grid, 256>>>(A, B, bias, C, M, Nc, K);
    else if (epi == 1) tf32gemm_kernel<1><<<grid, 256>>>(A, B, bias, C, M, Nc, K);
    else               tf32gemm_kernel<2><<<grid, 256>>>(A, B, bias, C, M, Nc, K);
}

extern "C" void kernel_launch(void* const* d_in, const int* in_sizes, int n_in,
                              void* d_out, int out_size)
{
    const float* x    = (const float*)d_in[0];
    const void*  ei   = d_in[1];
    const float* Wq   = (const float*)d_in[3];
    const float* Wk   = (const float*)d_in[4];
    const float* Wv   = (const float*)d_in[5];
    const float* Wo   = (const float*)d_in[6];
    const float* Wob  = (const float*)d_in[7];
    const float* ln1g = (const float*)d_in[8];
    const float* ln1b = (const float*)d_in[9];
    const float* ln2g = (const float*)d_in[10];
    const float* ln2b = (const float*)d_in[11];
    const float* W1   = (const float*)d_in[12];
    const float* b1   = (const float*)d_in[13];
    const float* W2   = (const float*)d_in[14];
    const float* b2   = (const float*)d_in[15];
    float* out = (float*)d_out;

    int N = in_sizes[0] / CDIM;
    int E = in_sizes[1] / 2;
    int nb = (N + 1023) / 1024;

    float *pQ, *pK, *pV, *pAttn, *pY1, *pH, *pT2;
    cudaGetSymbolAddress((void**)&pQ,    g_Q);
    cudaGetSymbolAddress((void**)&pK,    g_K);
    cudaGetSymbolAddress((void**)&pV,    g_V);
    cudaGetSymbolAddress((void**)&pAttn, g_attn);
    cudaGetSymbolAddress((void**)&pY1,   g_y1);
    cudaGetSymbolAddress((void**)&pH,    g_h);
    cudaGetSymbolAddress((void**)&pT2,   g_t2);

    // edge sort
    detect64_kernel<<<1, 1>>>(ei, N);
    zero_kernel      <<<(N + 255) / 256, 256>>>(N);
    hist_kernel      <<<(E + 255) / 256, 256>>>(ei, E);
    scan_block_kernel<<<nb, 1024>>>(N);
    scan_top_kernel  <<<1, 1>>>(nb, N);
    scan_add_kernel  <<<nb, 1024>>>(N);
    scatter_kernel   <<<(E + 255) / 256, 256>>>(ei, E);

    // Q/K/V projections
    launch_gemm(x, Wq, nullptr, pQ, N, 256, 256, 0);
    launch_gemm(x, Wk, nullptr, pK, N, 256, 256, 0);
    launch_gemm(x, Wv, nullptr, pV, N, 256, 256, 0);

    // fused edge attention (no atomics)
    edge_agg_kernel<<<(N * 32 + 255) / 256, 256>>>(N);

    // output projection + residual LN1
    launch_gemm(pAttn, Wo, Wob, pT2, N, 256, 256, 1);
    add_ln_kernel<<<(N * 32 + 255) / 256, 256>>>(x, pT2, ln1g, ln1b, pY1, N);

    // FFN
    launch_gemm(pY1, W1, b1, pH,  N, 512, 256, 2);   // + bias + exact GELU
    launch_gemm(pH,  W2, b2, pT2, N, 256, 512, 1);   // + bias
    add_ln_kernel<<<(N * 32 + 255) / 256, 256>>>(pY1, pT2, ln2g, ln2b, out, N);
}